// round 11
// baseline (speedup 1.0000x reference)
#include <cuda_runtime.h>
#include <cstdint>

// ---------------------------------------------------------------------------
// CRSD block: 2-layer leaky reservoir RNN.  B=32, T=1024, D=R=1024, ALPHA=0.1
// v4: 256 CTAs (2 per SM) so sync/wait bubbles of one CTA are hidden by the
// co-resident CTA's compute. Each CTA owns 4 r-cols + 4 h-cols. Odd CTAs walk
// chunks in reversed order (within x-half / h-half) to anti-phase the stalls.
// ---------------------------------------------------------------------------

#define B_DIM 32
#define T_DIM 1024
#define D_DIM 1024
#define TD_STRIDE (T_DIM * T_DIM)
#define GRID_CTAS 256
#define NTHR 256
#define CH_FLOATS 2048                 // 64 rows x 32 batch = 8KB chunk
#define NCH_A 32
#define NCH_B 16

typedef unsigned long long ull;

__device__ float g_buf[(size_t)T_DIM * D_DIM * B_DIM];  // [t][k][b]
__device__ float g_hT[D_DIM * B_DIM];                    // [k][b]
__device__ float g_rT[D_DIM * B_DIM];                    // [k][b]
__device__ unsigned g_bar_count = 0;
__device__ unsigned g_bar_epoch = 0;

// ---- packed fp32x2 helpers -------------------------------------------------
__device__ __forceinline__ ull pk2(float w) {
    ull r;
    asm("mov.b64 %0, {%1, %1};" : "=l"(r) : "f"(w));
    return r;
}
__device__ __forceinline__ void ffma2(ull& acc, ull a, ull w) {
    asm("fma.rn.f32x2 %0, %1, %2, %0;" : "+l"(acc) : "l"(a), "l"(w));
}

// ---- cp.async.cg -------------------------------------------------------------
__device__ __forceinline__ unsigned smem_u32(const void* p) {
    unsigned a;
    asm("{ .reg .u64 t; cvta.to.shared.u64 t, %1; cvt.u32.u64 %0, t; }"
        : "=r"(a) : "l"(p));
    return a;
}
#define CP_COMMIT_EMPTY() asm volatile("cp.async.commit_group;" ::: "memory")
#define CP_WAIT1()        asm volatile("cp.async.wait_group 1;" ::: "memory")

// copy one 8KB chunk (2048 floats) global->smem; 256 thr x 2 x 16B
__device__ __forceinline__ void cp_chunk8(float* dst, const float* src, int tid) {
    unsigned sb = smem_u32(dst) + tid * 16;
    const float* gp = src + tid * 4;
    asm volatile("cp.async.cg.shared.global [%0], [%1], 16;"
                 :: "r"(sb), "l"(gp) : "memory");
    asm volatile("cp.async.cg.shared.global [%0], [%1], 16;"
                 :: "r"(sb + 4096), "l"(gp + 1024) : "memory");
    asm volatile("cp.async.commit_group;" ::: "memory");
}

// ---- grid-wide barrier (256 CTAs, 2 per SM) ---------------------------------
__device__ __forceinline__ void grid_barrier(unsigned& epoch) {
    __syncthreads();
    if (threadIdx.x == 0) {
        unsigned next = epoch + 1u;
        __threadfence();
        unsigned old = atomicAdd(&g_bar_count, 1u);
        if (old == GRID_CTAS - 1u) {
            atomicExch(&g_bar_count, 0u);
            __threadfence();
            atomicExch(&g_bar_epoch, next);
        } else {
            while (*((volatile unsigned*)&g_bar_epoch) != next) { }
        }
        epoch = next;
    }
    __syncthreads();
}

// ---------------------------------------------------------------------------
// SMEM per CTA: WA[2048][8] (cols 0-3: Wxr/Whr, cols 4-7: Wxh/Whh),
// WB[1024][4] (Wrh), RED[8*8*32], Ps[128], Rs[128], ACT 2 x 8KB.
// Total = 16384+4096+2048+128+128+4096 floats = 107,520 B  (2 CTAs/SM fit).
// ---------------------------------------------------------------------------
#define SMEM_FLOATS (2048*8 + 1024*4 + 2048 + 128 + 128 + 2*CH_FLOATS)
#define SMEM_BYTES  (SMEM_FLOATS * 4)

__global__ void __launch_bounds__(NTHR, 2)
scan_kernel(const float* __restrict__ Wxh, const float* __restrict__ Whh,
            const float* __restrict__ Wrh, const float* __restrict__ Wxr,
            const float* __restrict__ Whr, int layer)
{
    extern __shared__ float sm[];
    float* WA  = sm;                    // 2048*8
    float* WB  = WA + 2048 * 8;         // 1024*4
    float* RED = WB + 1024 * 4;         // 2048
    float* Ps  = RED + 2048;            // 128
    float* Rs  = Ps + 128;              // 128
    float* ACT = Rs + 128;              // 2*2048

    const int tid  = threadIdx.x;
    const int cta  = blockIdx.x;
    const int c4   = cta * 4;
    const int lane = tid & 31;
    const int warp = tid >> 5;
    const int rev  = cta & 1;           // odd CTAs: reversed chunk order

    const size_t DR = (size_t)D_DIM * D_DIM;
    const float* wxh = Wxh + (size_t)layer * DR;
    const float* whh = Whh + (size_t)layer * DR;
    const float* wrh = Wrh + (size_t)layer * DR;
    const float* wxr = Wxr + (size_t)layer * DR;
    const float* whr = Whr + (size_t)layer * DR;

    // ---- weight slices -> SMEM (once per layer) ----
    for (int i = tid; i < 16384; i += NTHR) {        // WA[k][j]
        int k = i >> 3, j = i & 7;
        int kk = k & 1023;
        int col = c4 + (j & 3);
        const float* W = (j < 4) ? ((k < 1024) ? wxr : whr)
                                 : ((k < 1024) ? wxh : whh);
        WA[i] = W[(size_t)kk * D_DIM + col];
    }
    for (int i = tid; i < 4096; i += NTHR) {         // WB[k][j]
        int k = i >> 2, j = i & 3;
        WB[i] = wrh[(size_t)k * D_DIM + c4 + j];
    }
    // ---- zero state ----
    if (tid < 128) {
        Rs[tid] = 0.0f;
        int j = tid >> 5, b = tid & 31;
        g_hT[(c4 + j) * 32 + b] = 0.0f;
    }
    unsigned epoch = *((volatile unsigned*)&g_bar_epoch);
    __threadfence();
    grid_barrier(epoch);

    // lane maps
    const int jj  = lane >> 2;   // phase A: 0..7 (cols 0-3 r, 4-7 h)
    const int bb  = lane & 3;    // phase A: batch octet (8 floats)
    const int jj4 = lane >> 3;   // phase B: 0..3 cols
    const int bb8 = lane & 7;    // phase B: batch quad (4 floats)

    // chunk-index maps (odd CTAs reversed within each half)
    auto ciA = [&](int c) { return rev ? (c < 16 ? 15 - c : 47 - c) : c; };
    auto ciB = [&](int c) { return rev ? 15 - c : c; };

    // ---- t=0 phase-A prologue: 2 x-chunks (both parities map into x-half) ----
    {
        const float* xs = g_buf;
        cp_chunk8(ACT,             xs + ciA(0) * CH_FLOATS, tid);
        cp_chunk8(ACT + CH_FLOATS, xs + ciA(1) * CH_FLOATS, tid);
    }

    for (int t = 0; t < T_DIM; ++t) {
        const float* xsrc = g_buf + (size_t)t * (D_DIM * B_DIM);

        // ================= PHASE A =================
        // U[32,8] = [x_t ; h](32x2048) @ WA(2048x8); 32 chunks of 64 rows.
        {
            ull acc[4];
            #pragma unroll
            for (int i = 0; i < 4; ++i) acc[i] = 0ULL;

            #pragma unroll 1
            for (int c = 0; c < NCH_A; ++c) {
                CP_WAIT1();
                __syncthreads();

                int ci = ciA(c);
                const float* cb   = ACT + (c & 1) * CH_FLOATS;
                const float* arow = cb + warp * (8 * 32) + bb * 8;
                const float* wrow = WA + (ci * 64 + warp * 8) * 8;

                #pragma unroll
                for (int kl = 0; kl < 8; ++kl) {
                    ulonglong2 a01 = *(const ulonglong2*)(arow + kl * 32);
                    ulonglong2 a23 = *(const ulonglong2*)(arow + kl * 32 + 4);
                    ull wp = pk2(wrow[kl * 8 + jj]);
                    ffma2(acc[0], a01.x, wp);
                    ffma2(acc[1], a01.y, wp);
                    ffma2(acc[2], a23.x, wp);
                    ffma2(acc[3], a23.y, wp);
                }
                __syncthreads();
                int nc = c + 2;
                if (nc < NCH_A) {
                    int cin = ciA(nc);
                    const float* src = (cin < 16)
                        ? (xsrc + cin * CH_FLOATS)
                        : (g_hT + (cin - 16) * CH_FLOATS);
                    cp_chunk8(ACT + (c & 1) * CH_FLOATS, src, tid);
                } else {
                    CP_COMMIT_EMPTY();
                }
            }
            float* rw = RED + warp * 256;
            ull* p0 = (ull*)(rw + jj * 32 + bb * 8);
            p0[0] = acc[0]; p0[1] = acc[1]; p0[2] = acc[2]; p0[3] = acc[3];
        }
        __syncthreads();
        // reduce A: 8 cols x 32 batch, one output per thread
        {
            int o = tid;
            float s = 0.0f;
            #pragma unroll
            for (int w = 0; w < 8; ++w) s += RED[w * 256 + o];
            int j = o >> 5, b = o & 31;
            if (j < 4) {
                float g  = tanhf(s);
                float rn = 0.9f * Rs[o] + 0.1f * g;
                Rs[o] = rn;
                g_rT[(c4 + j) * 32 + b] = rn;
            } else {
                Ps[o - 128] = s;
            }
        }
        __threadfence();
        grid_barrier(epoch);   // r_new globally visible

        // ================= PHASE B =================
        // Z[32,4] = r_new(32x1024) @ WB(1024x4); 16 chunks of 64 rows.
        {
            cp_chunk8(ACT,             g_rT + ciB(0) * CH_FLOATS, tid);
            cp_chunk8(ACT + CH_FLOATS, g_rT + ciB(1) * CH_FLOATS, tid);

            ull acc[2];
            acc[0] = 0ULL; acc[1] = 0ULL;

            #pragma unroll 1
            for (int c = 0; c < NCH_B; ++c) {
                CP_WAIT1();
                __syncthreads();

                int ci = ciB(c);
                const float* cb   = ACT + (c & 1) * CH_FLOATS;
                const float* arow = cb + warp * (8 * 32) + bb8 * 4;
                const float* wrow = WB + (ci * 64 + warp * 8) * 4;

                #pragma unroll
                for (int kl = 0; kl < 8; ++kl) {
                    ulonglong2 a01 = *(const ulonglong2*)(arow + kl * 32);
                    ull wp = pk2(wrow[kl * 4 + jj4]);
                    ffma2(acc[0], a01.x, wp);
                    ffma2(acc[1], a01.y, wp);
                }
                __syncthreads();
                int nc = c + 2;
                if (nc < NCH_B) {
                    cp_chunk8(ACT + (c & 1) * CH_FLOATS,
                              g_rT + ciB(nc) * CH_FLOATS, tid);
                } else {
                    CP_COMMIT_EMPTY();
                }
            }
            float* rw = RED + warp * 128;
            ull* p0 = (ull*)(rw + jj4 * 32 + bb8 * 4);
            p0[0] = acc[0]; p0[1] = acc[1];
        }
        __syncthreads();
        // cross-step prefetch of next step's first 2 x-chunks (barrier-independent)
        if (t + 1 < T_DIM) {
            const float* nx = g_buf + (size_t)(t + 1) * (D_DIM * B_DIM);
            cp_chunk8(ACT,             nx + ciA(0) * CH_FLOATS, tid);
            cp_chunk8(ACT + CH_FLOATS, nx + ciA(1) * CH_FLOATS, tid);
        } else {
            CP_COMMIT_EMPTY(); CP_COMMIT_EMPTY();
        }
        // reduce B + h update
        if (tid < 128) {
            int o = tid;
            float z = 0.0f;
            #pragma unroll
            for (int w = 0; w < 8; ++w) z += RED[w * 128 + o];
            int j = o >> 5, b = o & 31;
            float hn = tanhf(Ps[o] + z);
            g_hT[(c4 + j) * 32 + b] = hn;
            g_buf[(size_t)t * (D_DIM * B_DIM) + (c4 + j) * 32 + b] = hn;
        }
        __threadfence();
        grid_barrier(epoch);   // h_new visible before next step
    }
}

// ---------------------------------------------------------------------------
// Transposes: x[b][t][k]  <->  buf[t][k][b]
// ---------------------------------------------------------------------------
__global__ void transpose_in(const float* __restrict__ x)
{
    __shared__ float s[32][65];
    const int t  = blockIdx.y;
    const int k0 = blockIdx.x * 64;
    const int tid = threadIdx.x;

    #pragma unroll
    for (int p = 0; p < 8; ++p) {
        int b  = p * 4 + (tid >> 6);
        int kk = tid & 63;
        s[b][kk] = x[(size_t)b * TD_STRIDE + (size_t)t * D_DIM + k0 + kk];
    }
    __syncthreads();
    #pragma unroll
    for (int p = 0; p < 8; ++p) {
        int kk = p * 8 + (tid >> 5);
        int b  = tid & 31;
        g_buf[(size_t)t * (D_DIM * B_DIM) + (size_t)(k0 + kk) * 32 + b] = s[b][kk];
    }
}

__global__ void transpose_out(float* __restrict__ out)
{
    __shared__ float s[64][33];
    const int t  = blockIdx.y;
    const int j0 = blockIdx.x * 64;
    const int tid = threadIdx.x;

    #pragma unroll
    for (int p = 0; p < 8; ++p) {
        int jj = p * 8 + (tid >> 5);
        int b  = tid & 31;
        s[jj][b] = g_buf[(size_t)t * (D_DIM * B_DIM) + (size_t)(j0 + jj) * 32 + b];
    }
    __syncthreads();
    #pragma unroll
    for (int p = 0; p < 8; ++p) {
        int b  = p * 4 + (tid >> 6);
        int jc = tid & 63;
        out[(size_t)b * TD_STRIDE + (size_t)t * D_DIM + j0 + jc] = s[jc][b];
    }
}

// ---------------------------------------------------------------------------
extern "C" void kernel_launch(void* const* d_in, const int* in_sizes, int n_in,
                              void* d_out, int out_size)
{
    const float* x   = (const float*)d_in[0];
    const float* Wxh = (const float*)d_in[1];
    const float* Whh = (const float*)d_in[2];
    const float* Wrh = (const float*)d_in[3];
    const float* Wxr = (const float*)d_in[4];
    const float* Whr = (const float*)d_in[5];
    float* out = (float*)d_out;

    cudaFuncSetAttribute(scan_kernel,
                         cudaFuncAttributeMaxDynamicSharedMemorySize,
                         SMEM_BYTES);

    transpose_in<<<dim3(16, 1024), NTHR>>>(x);
    scan_kernel<<<GRID_CTAS, NTHR, SMEM_BYTES>>>(Wxh, Whh, Wrh, Wxr, Whr, 0);
    scan_kernel<<<GRID_CTAS, NTHR, SMEM_BYTES>>>(Wxh, Whh, Wrh, Wxr, Whr, 1);
    transpose_out<<<dim3(16, 1024), NTHR>>>(out);
}

// round 12
// speedup vs baseline: 1.5675x; 1.5675x over previous
#include <cuda_runtime.h>
#include <cstdint>

// ---------------------------------------------------------------------------
// CRSD block: 2-layer leaky reservoir RNN.  B=32, T=1024, D=R=1024, ALPHA=0.1
// v5: 128 CTAs (1/SM), weights in SMEM. Key change vs v3: per-CTA ROTATED
// chunk order so the 128 CTAs' broadcast reads spread across all L2 slices
// instead of hammering the same 128 lines in lockstep. NBUF=3 ring with a
// single __syncthreads per chunk (issue-before-compute, uniform WAIT1).
// ---------------------------------------------------------------------------

#define B_DIM 32
#define T_DIM 1024
#define D_DIM 1024
#define TD_STRIDE (T_DIM * T_DIM)
#define GRID_CTAS 128
#define NTHR 256
#define CH 4096                        // chunk: 128 rows x 32 batch = 16KB
#define NBUF 3

typedef unsigned long long ull;

__device__ float g_buf[(size_t)T_DIM * D_DIM * B_DIM];  // [t][k][b]
__device__ float g_hT[D_DIM * B_DIM];                    // [k][b]
__device__ float g_rT[D_DIM * B_DIM];                    // [k][b]
__device__ unsigned g_bar_count = 0;
__device__ unsigned g_bar_epoch = 0;

// ---- packed fp32x2 helpers -------------------------------------------------
__device__ __forceinline__ ull pk2(float w) {
    ull r;
    asm("mov.b64 %0, {%1, %1};" : "=l"(r) : "f"(w));
    return r;
}
__device__ __forceinline__ void ffma2(ull& acc, ull a, ull w) {
    asm("fma.rn.f32x2 %0, %1, %2, %0;" : "+l"(acc) : "l"(a), "l"(w));
}

// ---- cp.async.cg (L2-sourced => coherent across SMs) ------------------------
__device__ __forceinline__ unsigned smem_u32(const void* p) {
    unsigned a;
    asm("{ .reg .u64 t; cvta.to.shared.u64 t, %1; cvt.u32.u64 %0, t; }"
        : "=r"(a) : "l"(p));
    return a;
}
#define CP_COMMIT_EMPTY() asm volatile("cp.async.commit_group;" ::: "memory")
#define CP_WAIT1()        asm volatile("cp.async.wait_group 1;" ::: "memory")

// copy one 16KB chunk global->smem; 256 threads x 4 x 16B; commits one group
__device__ __forceinline__ void cp_chunk(float* dst, const float* src, int tid) {
    unsigned sb = smem_u32(dst) + tid * 16;
    const float* gp = src + tid * 4;
    #pragma unroll
    for (int i = 0; i < 4; ++i) {
        asm volatile("cp.async.cg.shared.global [%0], [%1], 16;"
                     :: "r"(sb + i * 4096), "l"(gp + i * 1024) : "memory");
    }
    asm volatile("cp.async.commit_group;" ::: "memory");
}

// ---- grid-wide barrier (128 CTAs co-resident, 1/SM) -------------------------
__device__ __forceinline__ void grid_barrier(unsigned& epoch) {
    __syncthreads();
    if (threadIdx.x == 0) {
        unsigned next = epoch + 1u;
        __threadfence();
        unsigned old = atomicAdd(&g_bar_count, 1u);
        if (old == GRID_CTAS - 1u) {
            atomicExch(&g_bar_count, 0u);
            __threadfence();
            atomicExch(&g_bar_epoch, next);
        } else {
            while (*((volatile unsigned*)&g_bar_epoch) != next) { }
        }
        epoch = next;
    }
    __syncthreads();
}

// ---------------------------------------------------------------------------
// SMEM: WA[2048][16], WB[1024][8], RED[4096], Ps[256], Rs[256], ACT 3 x 16KB.
// Total = 57856 floats = 231,424 B.
// ---------------------------------------------------------------------------
#define SMEM_FLOATS (2048*16 + 1024*8 + 4096 + 256 + 256 + NBUF*CH)
#define SMEM_BYTES  (SMEM_FLOATS * 4)

__global__ void __launch_bounds__(NTHR, 1)
scan_kernel(const float* __restrict__ Wxh, const float* __restrict__ Whh,
            const float* __restrict__ Wrh, const float* __restrict__ Wxr,
            const float* __restrict__ Whr, int layer)
{
    extern __shared__ float sm[];
    float* WA  = sm;                        // 2048*16
    float* WB  = WA + 2048 * 16;            // 1024*8
    float* RED = WB + 1024 * 8;             // 4096
    float* Ps  = RED + 4096;                // 256
    float* Rs  = Ps + 256;                  // 256
    float* ACT = Rs + 256;                  // 3*4096

    const int tid  = threadIdx.x;
    const int cta  = blockIdx.x;
    const int c8   = cta * 8;
    const int lane = tid & 31;
    const int warp = tid >> 5;
    const int rot  = cta & 7;               // per-CTA chunk rotation

    const size_t DR = (size_t)D_DIM * D_DIM;
    const float* wxh = Wxh + (size_t)layer * DR;
    const float* whh = Whh + (size_t)layer * DR;
    const float* wrh = Wrh + (size_t)layer * DR;
    const float* wxr = Wxr + (size_t)layer * DR;
    const float* whr = Whr + (size_t)layer * DR;

    // ---- weight slices -> SMEM (once per layer) ----
    for (int i = tid; i < 8192; i += NTHR) {
        int k  = i >> 3;
        int jc = i & 7;
        int g  = k * D_DIM + c8 + jc;
        WA[k * 16 + jc]              = wxr[g];
        WA[k * 16 + 8 + jc]          = wxh[g];
        WA[(k + 1024) * 16 + jc]     = whr[g];
        WA[(k + 1024) * 16 + 8 + jc] = whh[g];
        WB[k * 8 + jc]               = wrh[g];
    }
    // ---- zero state ----
    {
        Rs[tid] = 0.0f;
        int j = tid >> 5, b = tid & 31;
        g_hT[(c8 + j) * 32 + b] = 0.0f;
    }
    unsigned epoch = *((volatile unsigned*)&g_bar_epoch);
    __threadfence();
    grid_barrier(epoch);

    const int jj = lane >> 2;   // 0..7
    const int bb = lane & 3;    // 0..3

    // rotated chunk maps (per half, so chunks A0/A1 are always x-half)
    auto ciA = [&](int c) -> int {
        return (c < 8) ? ((c + rot) & 7) : (8 + ((c + rot) & 7));
    };
    auto ciB = [&](int c) -> int { return (c + rot) & 7; };

    int ibuf = 0, cbuf = 0;     // ring positions for issue / consume

    // ---- t=0 phase-A prologue: chunks A0, A1 ----
    cp_chunk(ACT + ibuf * CH, g_buf + ciA(0) * CH, tid); ibuf = 1;
    cp_chunk(ACT + ibuf * CH, g_buf + ciA(1) * CH, tid); ibuf = 2;

    for (int t = 0; t < T_DIM; ++t) {
        const float* xsrc = g_buf + (size_t)t * (D_DIM * B_DIM);

        // ================= PHASE A =================
        // U[32,16] = [x_t ; h](32x2048) @ WA(2048x16); 16 chunks of 128 rows.
        {
            ull acc[8];
            #pragma unroll
            for (int i = 0; i < 8; ++i) acc[i] = 0ULL;

            #pragma unroll 1
            for (int c = 0; c < 16; ++c) {
                CP_WAIT1();                 // group holding chunk c is done
                __syncthreads();            // also: prev iter's reads finished

                int nc = c + 2;
                if (nc < 16) {              // issue ahead (overlaps compute)
                    int cin = ciA(nc);
                    const float* src = (cin < 8)
                        ? (xsrc + cin * CH)
                        : (g_hT + (cin - 8) * CH);
                    cp_chunk(ACT + ibuf * CH, src, tid);
                    ibuf = (ibuf == 2) ? 0 : ibuf + 1;
                } else {
                    CP_COMMIT_EMPTY();
                }

                int ci = ciA(c);
                const float* cb   = ACT + cbuf * CH;
                cbuf = (cbuf == 2) ? 0 : cbuf + 1;
                const float* arow = cb + warp * (16 * 32) + bb * 8;
                const float* wrow = WA + (ci * 128 + warp * 16) * 16;

                #pragma unroll
                for (int kl = 0; kl < 16; ++kl) {
                    ulonglong2 a01 = *(const ulonglong2*)(arow + kl * 32);
                    ulonglong2 a23 = *(const ulonglong2*)(arow + kl * 32 + 4);
                    ull wp0 = pk2(wrow[kl * 16 + jj]);
                    ull wp1 = pk2(wrow[kl * 16 + 8 + jj]);
                    ffma2(acc[0], a01.x, wp0);
                    ffma2(acc[1], a01.y, wp0);
                    ffma2(acc[2], a23.x, wp0);
                    ffma2(acc[3], a23.y, wp0);
                    ffma2(acc[4], a01.x, wp1);
                    ffma2(acc[5], a01.y, wp1);
                    ffma2(acc[6], a23.x, wp1);
                    ffma2(acc[7], a23.y, wp1);
                }
            }

            float* rw = RED + warp * 512;
            ull* p0 = (ull*)(rw + jj * 32 + bb * 8);
            p0[0] = acc[0]; p0[1] = acc[1]; p0[2] = acc[2]; p0[3] = acc[3];
            ull* p1 = (ull*)(rw + (jj + 8) * 32 + bb * 8);
            p1[0] = acc[4]; p1[1] = acc[5]; p1[2] = acc[6]; p1[3] = acc[7];
        }
        __syncthreads();
        // cross-warp reduce + r update / p stash
        #pragma unroll
        for (int o = tid; o < 512; o += NTHR) {
            float s = 0.0f;
            #pragma unroll
            for (int w = 0; w < 8; ++w) s += RED[w * 512 + o];
            int j = o >> 5, b = o & 31;
            if (j < 8) {
                float g  = tanhf(s);
                float rn = 0.9f * Rs[o] + 0.1f * g;
                Rs[o] = rn;
                g_rT[(c8 + j) * 32 + b] = rn;
            } else {
                Ps[o - 256] = s;
            }
        }
        __threadfence();
        grid_barrier(epoch);   // r_new globally visible

        // ================= PHASE B =================
        // Z[32,8] = r_new(32x1024) @ WB(1024x8); 8 chunks of 128 rows.
        {
            // prologue: first two r-chunks (post-barrier)
            cp_chunk(ACT + ibuf * CH, g_rT + ciB(0) * CH, tid);
            ibuf = (ibuf == 2) ? 0 : ibuf + 1;
            cp_chunk(ACT + ibuf * CH, g_rT + ciB(1) * CH, tid);
            ibuf = (ibuf == 2) ? 0 : ibuf + 1;

            ull acc[4];
            #pragma unroll
            for (int i = 0; i < 4; ++i) acc[i] = 0ULL;

            #pragma unroll 1
            for (int c = 0; c < 8; ++c) {
                CP_WAIT1();
                __syncthreads();

                int nc = c + 2;
                if (nc < 8) {
                    cp_chunk(ACT + ibuf * CH, g_rT + ciB(nc) * CH, tid);
                    ibuf = (ibuf == 2) ? 0 : ibuf + 1;
                } else if (t + 1 < T_DIM) {
                    // cross-step prefetch of next step's A chunks 0/1 (x-half,
                    // independent of the upcoming barrier)
                    const float* nx = g_buf + (size_t)(t + 1) * (D_DIM * B_DIM);
                    cp_chunk(ACT + ibuf * CH, nx + ciA(nc - 8) * CH, tid);
                    ibuf = (ibuf == 2) ? 0 : ibuf + 1;
                } else {
                    CP_COMMIT_EMPTY();
                }

                int ci = ciB(c);
                const float* cb   = ACT + cbuf * CH;
                cbuf = (cbuf == 2) ? 0 : cbuf + 1;
                const float* arow = cb + warp * (16 * 32) + bb * 8;
                const float* wrow = WB + (ci * 128 + warp * 16) * 8;

                #pragma unroll
                for (int kl = 0; kl < 16; ++kl) {
                    ulonglong2 a01 = *(const ulonglong2*)(arow + kl * 32);
                    ulonglong2 a23 = *(const ulonglong2*)(arow + kl * 32 + 4);
                    ull wp = pk2(wrow[kl * 8 + jj]);
                    ffma2(acc[0], a01.x, wp);
                    ffma2(acc[1], a01.y, wp);
                    ffma2(acc[2], a23.x, wp);
                    ffma2(acc[3], a23.y, wp);
                }
            }

            float* rw = RED + warp * 256;
            ull* p0 = (ull*)(rw + jj * 32 + bb * 8);
            p0[0] = acc[0]; p0[1] = acc[1]; p0[2] = acc[2]; p0[3] = acc[3];
        }
        __syncthreads();
        {
            float z = 0.0f;
            #pragma unroll
            for (int w = 0; w < 8; ++w) z += RED[w * 256 + tid];
            int j = tid >> 5, b = tid & 31;
            float hn = tanhf(Ps[tid] + z);
            g_hT[(c8 + j) * 32 + b] = hn;
            g_buf[(size_t)t * (D_DIM * B_DIM) + (c8 + j) * 32 + b] = hn;
        }
        __threadfence();
        grid_barrier(epoch);   // h_new visible before next step
    }
}

// ---------------------------------------------------------------------------
// Transposes: x[b][t][k]  <->  buf[t][k][b]
// ---------------------------------------------------------------------------
__global__ void transpose_in(const float* __restrict__ x)
{
    __shared__ float s[32][65];
    const int t  = blockIdx.y;
    const int k0 = blockIdx.x * 64;
    const int tid = threadIdx.x;

    #pragma unroll
    for (int p = 0; p < 8; ++p) {
        int b  = p * 4 + (tid >> 6);
        int kk = tid & 63;
        s[b][kk] = x[(size_t)b * TD_STRIDE + (size_t)t * D_DIM + k0 + kk];
    }
    __syncthreads();
    #pragma unroll
    for (int p = 0; p < 8; ++p) {
        int kk = p * 8 + (tid >> 5);
        int b  = tid & 31;
        g_buf[(size_t)t * (D_DIM * B_DIM) + (size_t)(k0 + kk) * 32 + b] = s[b][kk];
    }
}

__global__ void transpose_out(float* __restrict__ out)
{
    __shared__ float s[64][33];
    const int t  = blockIdx.y;
    const int j0 = blockIdx.x * 64;
    const int tid = threadIdx.x;

    #pragma unroll
    for (int p = 0; p < 8; ++p) {
        int jj = p * 8 + (tid >> 5);
        int b  = tid & 31;
        s[jj][b] = g_buf[(size_t)t * (D_DIM * B_DIM) + (size_t)(j0 + jj) * 32 + b];
    }
    __syncthreads();
    #pragma unroll
    for (int p = 0; p < 8; ++p) {
        int b  = p * 4 + (tid >> 6);
        int jc = tid & 63;
        out[(size_t)b * TD_STRIDE + (size_t)t * D_DIM + j0 + jc] = s[jc][b];
    }
}

// ---------------------------------------------------------------------------
extern "C" void kernel_launch(void* const* d_in, const int* in_sizes, int n_in,
                              void* d_out, int out_size)
{
    const float* x   = (const float*)d_in[0];
    const float* Wxh = (const float*)d_in[1];
    const float* Whh = (const float*)d_in[2];
    const float* Wrh = (const float*)d_in[3];
    const float* Wxr = (const float*)d_in[4];
    const float* Whr = (const float*)d_in[5];
    float* out = (float*)d_out;

    cudaFuncSetAttribute(scan_kernel,
                         cudaFuncAttributeMaxDynamicSharedMemorySize,
                         SMEM_BYTES);

    transpose_in<<<dim3(16, 1024), NTHR>>>(x);
    scan_kernel<<<GRID_CTAS, NTHR, SMEM_BYTES>>>(Wxh, Whh, Wrh, Wxr, Whr, 0);
    scan_kernel<<<GRID_CTAS, NTHR, SMEM_BYTES>>>(Wxh, Whh, Wrh, Wxr, Whr, 1);
    transpose_out<<<dim3(16, 1024), NTHR>>>(out);
}